// round 10
// baseline (speedup 1.0000x reference)
#include <cuda_runtime.h>
#include <cstdint>

#define FULLMASK 0xffffffffu

constexpr int T_ = 256;
constexpr int C_ = 128;
constexpr int L_ = 32;
constexpr int BLANK = 127;   // C-1
constexpr float EPSF = 1e-7f;
constexpr int DEPTH = 8;     // cp.async ring depth

__device__ __forceinline__ uint32_t smem_u32(const void* p) {
    uint32_t a;
    asm("{ .reg .u64 t; cvta.to.shared.u64 t, %1; cvt.u32.u64 %0, t; }"
        : "=r"(a) : "l"(p));
    return a;
}
__device__ __forceinline__ void cp16(uint32_t dst, const float* src) {
    asm volatile("cp.async.cg.shared.global [%0], [%1], 16;"
                 :: "r"(dst), "l"(src) : "memory");
}
#define CP_COMMIT() asm volatile("cp.async.commit_group;" ::: "memory")
#define CP_WAIT7()  asm volatile("cp.async.wait_group 7;" ::: "memory")

// One warp per block; one batch element per warp.
// PAIRED state layout: lane i owns s=2i (aEven, always a BLANK state) and
// s=2i+1 (aOdd, label i). Lane 31 additionally owns s=64 (aTop, blank).
//  - even update:  a'(2i)   = (a(2i)   + a(2i-1)) * pBlank
//  - odd  update:  a'(2i+1) = (a(2i+1) + a(2i) + skip_i * a(2i-1)) * p[lab_i]
//  - top  update:  a'(64)   = (a(64)   + a(63)) * pBlank          (lane 31 local)
// => a(2i-1) = shfl_up(aOdd,1) is the ONLY cross-lane value per step.
// Emissions: pBlank is an LDS broadcast; p[lab_i] is one gathered LDS.
// Probability-domain alphas (fp32), rescale every 4 steps, applied 2 steps later.
__global__ __launch_bounds__(32)
void ctc_alpha_kernel(const int* __restrict__ y_true_i32,
                      const float* __restrict__ y_pred,
                      float* __restrict__ out)
{
    const int lane = threadIdx.x;          // blockDim.x == 32
    const int b    = blockIdx.x;

    __shared__ float ring[DEPTH][C_];      // 4KB ring of prob rows
    const uint32_t ring_base = smem_u32(&ring[0][0]);

    const float* row = y_pred + (size_t)b * T_ * C_;

    // ---- label dtype detection (int32 vs int64 low-word); first 32 words in-bounds
    int w0 = y_true_i32[lane];
    unsigned zmask = __ballot_sync(FULLMASK, w0 == 0);
    bool is64 = ((zmask & 0xAAAAAAAAu) == 0xAAAAAAAAu);

    int lab = is64 ? y_true_i32[((size_t)b * L_ + lane) * 2]
                   : y_true_i32[(size_t)b * L_ + lane];
    lab &= 127;

    // skip permission for odd state s=2*lane+1: labels differ and lane >= 1
    int labPrev = __shfl_up_sync(FULLMASK, lab, 1);
    const float skip = (lane >= 1 && lab != labPrev) ? 1.0f : 0.0f;

    // ---- prologue: fill ring with rows 1..8 (one commit group per row)
    #pragma unroll
    for (int k = 1; k <= DEPTH; ++k) {
        int slot = k & (DEPTH - 1);
        cp16(ring_base + (slot * C_) * 4 + lane * 16, row + (size_t)k * C_ + lane * 4);
        CP_COMMIT();
    }

    // ---- t = 0 init: alpha(0)=p0[BLANK], alpha(1)=p0[lab0], on lane 0
    float aEven = 0.f, aOdd = 0.f, aTop = 0.f;
    if (lane == 0) {
        aEven = row[BLANK] + EPSF;
        aOdd  = row[lab]   + EPSF;
    }

    float r = aEven + aOdd;
    #pragma unroll
    for (int d = 16; d; d >>= 1) r += __shfl_xor_sync(FULLMASK, r, d);
    float acc  = __logf(r);
    float pend = __fdividef(1.0f, r);

    // ---- gather row 1 probs ahead of the loop
    CP_WAIT7();
    __syncwarp();
    float cB = ring[1][BLANK];   // broadcast
    float cL = ring[1][lab];     // gather

    #pragma unroll 4
    for (int t = 1; t < T_; ++t) {
        // apply (possibly deferred) scale to the pre-gathered probs
        float ic = ((t & 3) == 2) ? pend : 1.0f;
        float e  = EPSF * ic;
        float pB = fmaf(cB, ic, e);
        float pL = fmaf(cL, ic, e);

        // refill ring: row t+8 into slot t&7 (consumers of that slot long done)
        int tn = (t + DEPTH < T_) ? (t + DEPTH) : (T_ - 1);
        int ws = t & (DEPTH - 1);
        cp16(ring_base + (ws * C_) * 4 + lane * 16, row + (size_t)tn * C_ + lane * 4);
        CP_COMMIT();
        CP_WAIT7();          // row t+1 guaranteed complete
        __syncwarp();

        // gather probs for t+1 (overlaps the alpha chain below)
        int ts = (t + 1 < T_) ? (t + 1) : (T_ - 1);
        const float* g = &ring[ts & (DEPTH - 1)][0];
        cB = g[BLANK]; cL = g[lab];

        // the single cross-lane value: a(2i-1) = odd state of lane-1
        float oddPrev = __shfl_up_sync(FULLMASK, aOdd, 1);
        if (lane == 0) oddPrev = 0.f;

        float nEven = (aEven + oddPrev) * pB;
        float nOdd  = fmaf(skip, oddPrev, aOdd + aEven) * pL;
        float nTop  = (aTop + aOdd) * pB;       // lane 31: s=64 (a(63)=aOdd local)
        aEven = nEven; aOdd = nOdd; aTop = nTop;

        // periodic rescale: reduce at t%4==0, result applied at t+2 (off critical path)
        if ((t & 3) == 0) {
            float s = nEven + nOdd + ((lane == 31) ? nTop : 0.f);
            #pragma unroll
            for (int d = 16; d; d >>= 1) s += __shfl_xor_sync(FULLMASK, s, d);
            acc += __logf(s);
            pend = __fdividef(1.0f, s);
        }
    }

    // loss = -( log(alpha[64] + alpha[63]) + sum of applied log-scales )
    if (lane == 31) {
        out[b] = -(__logf(aTop + aOdd) + acc);
    }
}

extern "C" void kernel_launch(void* const* d_in, const int* in_sizes, int n_in,
                              void* d_out, int out_size) {
    // Identify inputs by size: y_true has B*L elements, y_pred has B*T*C.
    int idx_small = 0, idx_big = 1;
    if (in_sizes[0] > in_sizes[1]) { idx_small = 1; idx_big = 0; }

    const int*   y_true = (const int*)d_in[idx_small];   // int32 view; width detected in-kernel
    const float* y_pred = (const float*)d_in[idx_big];
    float*       out    = (float*)d_out;

    int B = in_sizes[idx_big] / (T_ * C_);   // 1024
    ctc_alpha_kernel<<<B, 32>>>(y_true, y_pred, out);
}

// round 11
// speedup vs baseline: 1.0082x; 1.0082x over previous
#include <cuda_runtime.h>
#include <cstdint>

#define FULLMASK 0xffffffffu

constexpr int T_ = 256;
constexpr int C_ = 128;
constexpr int L_ = 32;
constexpr int BLANK = 127;   // C-1
constexpr float EPSF = 1e-7f;
constexpr int DEPTH = 8;     // cp.async ring depth

__device__ __forceinline__ uint32_t smem_u32(const void* p) {
    uint32_t a;
    asm("{ .reg .u64 t; cvta.to.shared.u64 t, %1; cvt.u32.u64 %0, t; }"
        : "=r"(a) : "l"(p));
    return a;
}
__device__ __forceinline__ void cp16(uint32_t dst, const float* src) {
    asm volatile("cp.async.cg.shared.global [%0], [%1], 16;"
                 :: "r"(dst), "l"(src) : "memory");
}
#define CP_COMMIT() asm volatile("cp.async.commit_group;" ::: "memory")
#define CP_WAIT7()  asm volatile("cp.async.wait_group 7;" ::: "memory")

// One warp per block; one batch element per warp.
// PAIRED state layout: lane i owns s=2i (aEven, always a BLANK state) and
// s=2i+1 (aOdd, label i). Lane 31 additionally owns s=64 (aTop, blank).
//  - even update:  a'(2i)   = (a(2i)   + a(2i-1)) * pBlank
//  - odd  update:  a'(2i+1) = (a(2i+1) + a(2i) + skip_i * a(2i-1)) * p[lab_i]
//  - top  update:  a'(64)   = (a(64)   + a(63)) * pBlank          (lane 31 local)
// => a(2i-1) = shfl_up(aOdd,1) is the ONLY cross-lane value per step.
// Emissions: pBlank is an LDS broadcast; p[lab_i] is one gathered LDS.
// Probability-domain alphas (fp32), rescale every 4 steps, applied 2 steps later.
__global__ __launch_bounds__(32)
void ctc_alpha_kernel(const int* __restrict__ y_true_i32,
                      const float* __restrict__ y_pred,
                      float* __restrict__ out)
{
    const int lane = threadIdx.x;          // blockDim.x == 32
    const int b    = blockIdx.x;

    __shared__ float ring[DEPTH][C_];      // 4KB ring of prob rows
    const uint32_t ring_base = smem_u32(&ring[0][0]);

    const float* row = y_pred + (size_t)b * T_ * C_;

    // ---- label dtype detection (int32 vs int64 low-word); first 32 words in-bounds
    int w0 = y_true_i32[lane];
    unsigned zmask = __ballot_sync(FULLMASK, w0 == 0);
    bool is64 = ((zmask & 0xAAAAAAAAu) == 0xAAAAAAAAu);

    int lab = is64 ? y_true_i32[((size_t)b * L_ + lane) * 2]
                   : y_true_i32[(size_t)b * L_ + lane];
    lab &= 127;

    // skip permission for odd state s=2*lane+1: labels differ and lane >= 1
    int labPrev = __shfl_up_sync(FULLMASK, lab, 1);
    const float skip = (lane >= 1 && lab != labPrev) ? 1.0f : 0.0f;

    // ---- prologue: fill ring with rows 1..8 (one commit group per row)
    #pragma unroll
    for (int k = 1; k <= DEPTH; ++k) {
        int slot = k & (DEPTH - 1);
        cp16(ring_base + (slot * C_) * 4 + lane * 16, row + (size_t)k * C_ + lane * 4);
        CP_COMMIT();
    }

    // ---- t = 0 init: alpha(0)=p0[BLANK], alpha(1)=p0[lab0], on lane 0
    float aEven = 0.f, aOdd = 0.f, aTop = 0.f;
    if (lane == 0) {
        aEven = row[BLANK] + EPSF;
        aOdd  = row[lab]   + EPSF;
    }

    float r = aEven + aOdd;
    #pragma unroll
    for (int d = 16; d; d >>= 1) r += __shfl_xor_sync(FULLMASK, r, d);
    float acc  = __logf(r);
    float pend = __fdividef(1.0f, r);

    // ---- gather row 1 probs ahead of the loop
    CP_WAIT7();
    __syncwarp();
    float cB = ring[1][BLANK];   // broadcast
    float cL = ring[1][lab];     // gather

    #pragma unroll 4
    for (int t = 1; t < T_; ++t) {
        // apply (possibly deferred) scale to the pre-gathered probs
        float ic = ((t & 3) == 2) ? pend : 1.0f;
        float e  = EPSF * ic;
        float pB = fmaf(cB, ic, e);
        float pL = fmaf(cL, ic, e);

        // refill ring: row t+8 into slot t&7 (consumers of that slot long done)
        int tn = (t + DEPTH < T_) ? (t + DEPTH) : (T_ - 1);
        int ws = t & (DEPTH - 1);
        cp16(ring_base + (ws * C_) * 4 + lane * 16, row + (size_t)tn * C_ + lane * 4);
        CP_COMMIT();
        CP_WAIT7();          // row t+1 guaranteed complete
        __syncwarp();

        // gather probs for t+1 (overlaps the alpha chain below)
        int ts = (t + 1 < T_) ? (t + 1) : (T_ - 1);
        const float* g = &ring[ts & (DEPTH - 1)][0];
        cB = g[BLANK]; cL = g[lab];

        // the single cross-lane value: a(2i-1) = odd state of lane-1
        float oddPrev = __shfl_up_sync(FULLMASK, aOdd, 1);
        if (lane == 0) oddPrev = 0.f;

        float nEven = (aEven + oddPrev) * pB;
        float nOdd  = fmaf(skip, oddPrev, aOdd + aEven) * pL;
        float nTop  = (aTop + aOdd) * pB;       // lane 31: s=64 (a(63)=aOdd local)
        aEven = nEven; aOdd = nOdd; aTop = nTop;

        // periodic rescale: reduce at t%4==0, result applied at t+2 (off critical path)
        if ((t & 3) == 0) {
            float s = nEven + nOdd + ((lane == 31) ? nTop : 0.f);
            #pragma unroll
            for (int d = 16; d; d >>= 1) s += __shfl_xor_sync(FULLMASK, s, d);
            acc += __logf(s);
            pend = __fdividef(1.0f, s);
        }
    }

    // loss = -( log(alpha[64] + alpha[63]) + sum of applied log-scales )
    if (lane == 31) {
        out[b] = -(__logf(aTop + aOdd) + acc);
    }
}

extern "C" void kernel_launch(void* const* d_in, const int* in_sizes, int n_in,
                              void* d_out, int out_size) {
    // Identify inputs by size: y_true has B*L elements, y_pred has B*T*C.
    int idx_small = 0, idx_big = 1;
    if (in_sizes[0] > in_sizes[1]) { idx_small = 1; idx_big = 0; }

    const int*   y_true = (const int*)d_in[idx_small];   // int32 view; width detected in-kernel
    const float* y_pred = (const float*)d_in[idx_big];
    float*       out    = (float*)d_out;

    int B = in_sizes[idx_big] / (T_ * C_);   // 1024
    ctc_alpha_kernel<<<B, 32>>>(y_true, y_pred, out);
}